// round 1
// baseline (speedup 1.0000x reference)
#include <cuda_runtime.h>

// Problem constants (from reference_code)
#define C_IN   273
#define D_OUT  273
#define T_DIM  360
#define N_BATCH 256

// Tiling
#define BM 64     // d tile
#define BN 128    // t tile
#define BK 16     // c tile
#define NTHREADS 256
#define NK_ITERS ((C_IN + BK - 1) / BK)   // 18

// Decoded subject ids (handles int64-vs-int32 ambiguity of the input)
__device__ int g_subj[N_BATCH];

__global__ void decode_subjects_kernel(const void* __restrict__ subj_raw) {
    __shared__ int is64_s;
    const int tid = threadIdx.x;
    if (tid == 0) {
        // Read only the first 128 int64 slots (1024 bytes) — safe whether the
        // buffer holds 256 int32 (1024 B) or 256 int64 (2048 B).
        const long long* ll = (const long long*)subj_raw;
        int ok = 1;
        for (int i = 0; i < 128; ++i) {
            long long v = ll[i];
            if (v < 0 || v >= 128) { ok = 0; break; }
        }
        is64_s = ok;
    }
    __syncthreads();
    const int is64 = is64_s;
    for (int b = tid; b < N_BATCH; b += blockDim.x) {
        int s;
        if (is64) s = (int)(((const long long*)subj_raw)[b]);
        else      s = ((const int*)subj_raw)[b];
        g_subj[b] = s;
    }
}

// out[b,d,t] = sum_c W[s_b, c, d] * x[b, c, t]
// A-tile (As): W slice  [BK c-rows][BM d-cols]  (d contiguous in gmem)
// B-tile (Bs): x slice  [BK c-rows][BN t-cols]  (t contiguous in gmem)
__global__ __launch_bounds__(NTHREADS)
void subject_gemm_kernel(const float* __restrict__ x,
                         const float* __restrict__ w,
                         float* __restrict__ out) {
    const int b  = blockIdx.z;
    const int d0 = blockIdx.y * BM;
    const int t0 = blockIdx.x * BN;
    const int s  = g_subj[b];

    const float* __restrict__ W = w   + (long long)s * C_IN * D_OUT;
    const float* __restrict__ X = x   + (long long)b * C_IN * T_DIM;
    float*       __restrict__ O = out + (long long)b * D_OUT * T_DIM;

    __shared__ float As[BK][BM];
    __shared__ float Bs[BK][BN];

    const int tid = threadIdx.x;
    const int tx  = tid & 15;    // 0..15 -> t groups
    const int ty  = tid >> 4;    // 0..15 -> d groups

    float acc[4][8];
    #pragma unroll
    for (int i = 0; i < 4; ++i)
        #pragma unroll
        for (int j = 0; j < 8; ++j)
            acc[i][j] = 0.0f;

    // Register staging for global->smem double buffering
    float  aReg[4];
    float4 bReg[2];

    // ---- load helpers (inlined manually via lambdas not allowed; use macros) ----
    // A: 16x64 floats = 1024, 4 scalar loads/thread (W rows only 4B-aligned)
    // B: 16x128 floats = 2048 = 512 float4, 2 float4 loads/thread
    #define LOAD_TILE_REGS(c0)                                                 \
        {                                                                      \
            _Pragma("unroll")                                                  \
            for (int l = 0; l < 4; ++l) {                                      \
                int idx = tid + l * NTHREADS;                                  \
                int r   = idx >> 6;                                            \
                int col = idx & 63;                                            \
                int c   = (c0) + r;                                            \
                int d   = d0 + col;                                            \
                float v = 0.0f;                                                \
                if (c < C_IN && d < D_OUT)                                     \
                    v = __ldg(&W[(long long)c * D_OUT + d]);                   \
                aReg[l] = v;                                                   \
            }                                                                  \
            _Pragma("unroll")                                                  \
            for (int l = 0; l < 2; ++l) {                                      \
                int idx  = tid + l * NTHREADS;                                 \
                int r    = idx >> 5;                                           \
                int col  = (idx & 31) * 4;                                     \
                int c    = (c0) + r;                                           \
                int t    = t0 + col;                                           \
                float4 v = make_float4(0.f, 0.f, 0.f, 0.f);                    \
                if (c < C_IN && t < T_DIM)                                     \
                    v = *(const float4*)&X[(long long)c * T_DIM + t];          \
                bReg[l] = v;                                                   \
            }                                                                  \
        }

    #define STORE_TILE_SMEM()                                                  \
        {                                                                      \
            _Pragma("unroll")                                                  \
            for (int l = 0; l < 4; ++l) {                                      \
                int idx = tid + l * NTHREADS;                                  \
                int r   = idx >> 6;                                            \
                int col = idx & 63;                                            \
                As[r][col] = aReg[l];                                          \
            }                                                                  \
            _Pragma("unroll")                                                  \
            for (int l = 0; l < 2; ++l) {                                      \
                int idx = tid + l * NTHREADS;                                  \
                int r   = idx >> 5;                                            \
                int col = (idx & 31) * 4;                                      \
                *(float4*)&Bs[r][col] = bReg[l];                               \
            }                                                                  \
        }

    LOAD_TILE_REGS(0);

    for (int it = 0; it < NK_ITERS; ++it) {
        STORE_TILE_SMEM();
        __syncthreads();

        if (it + 1 < NK_ITERS) {
            const int c0n = (it + 1) * BK;
            LOAD_TILE_REGS(c0n);
        }

        #pragma unroll
        for (int k = 0; k < BK; ++k) {
            const float4 a  = *(const float4*)&As[k][ty * 4];
            const float4 b0 = *(const float4*)&Bs[k][tx * 4];
            const float4 b1 = *(const float4*)&Bs[k][tx * 4 + 64];
            const float av[4] = {a.x, a.y, a.z, a.w};
            const float bv[8] = {b0.x, b0.y, b0.z, b0.w,
                                 b1.x, b1.y, b1.z, b1.w};
            #pragma unroll
            for (int i = 0; i < 4; ++i)
                #pragma unroll
                for (int j = 0; j < 8; ++j)
                    acc[i][j] = fmaf(av[i], bv[j], acc[i][j]);
        }
        __syncthreads();
    }

    // Epilogue: d rows (guard d<273), two float4 groups in t (guard t<360; T%4==0)
    #pragma unroll
    for (int i = 0; i < 4; ++i) {
        const int d = d0 + ty * 4 + i;
        if (d < D_OUT) {
            float* row = O + (long long)d * T_DIM;
            const int t1 = t0 + tx * 4;
            if (t1 < T_DIM)
                *(float4*)&row[t1] = make_float4(acc[i][0], acc[i][1],
                                                 acc[i][2], acc[i][3]);
            const int t2 = t1 + 64;
            if (t2 < T_DIM)
                *(float4*)&row[t2] = make_float4(acc[i][4], acc[i][5],
                                                 acc[i][6], acc[i][7]);
        }
    }

    #undef LOAD_TILE_REGS
    #undef STORE_TILE_SMEM
}

extern "C" void kernel_launch(void* const* d_in, const int* in_sizes, int n_in,
                              void* d_out, int out_size) {
    const float* x        = (const float*)d_in[0];
    const void*  subjects = d_in[1];
    const float* weights  = (const float*)d_in[2];
    float* out            = (float*)d_out;

    decode_subjects_kernel<<<1, 256>>>(subjects);

    dim3 grid((T_DIM + BN - 1) / BN,    // 3
              (D_OUT + BM - 1) / BM,    // 5
              N_BATCH);                 // 256
    subject_gemm_kernel<<<grid, NTHREADS>>>(x, weights, out);
}

// round 3
// speedup vs baseline: 1.5019x; 1.5019x over previous
#include <cuda_runtime.h>
#include <cuda_bf16.h>
#include <cstdint>

// ---------------- problem constants ----------------
#define C_IN    273
#define D_OUT   273
#define T_DIM   360
#define N_BATCH 256

// ---------------- tiling ----------------
#define BM 128
#define BN 128
#define BK 32
#define NCH 9          // ceil(273/32)
#define NTH 256

// SMEM stage layout (bf16 tiles, 32 rows x 128 cols each)
#define ST_A_HI 0
#define ST_A_LO 8192
#define ST_B_HI 16384
#define ST_B_LO 24576
#define STAGE_SZ 32768
#define SMEM_TOTAL (2 * STAGE_SZ)   // 65536

__device__ int g_subj[N_BATCH];

__global__ void decode_subjects_kernel(const void* __restrict__ subj_raw) {
    __shared__ int is64_s;
    const int tid = threadIdx.x;
    if (tid == 0) {
        const long long* ll = (const long long*)subj_raw;
        int ok = 1;
        for (int i = 0; i < 128; ++i) {         // reads only first 1024 B
            long long v = ll[i];
            if (v < 0 || v >= 128) { ok = 0; break; }
        }
        is64_s = ok;
    }
    __syncthreads();
    const int is64 = is64_s;
    for (int b = tid; b < N_BATCH; b += blockDim.x) {
        g_subj[b] = is64 ? (int)(((const long long*)subj_raw)[b])
                         : ((const int*)subj_raw)[b];
    }
}

// ---------------- PTX helpers (sm_80-level ISA only) ----------------
#define LDSM_X4_T(r0, r1, r2, r3, addr)                                        \
    asm volatile("ldmatrix.sync.aligned.m8n8.x4.trans.shared.b16 "             \
                 "{%0,%1,%2,%3}, [%4];"                                        \
                 : "=r"(r0), "=r"(r1), "=r"(r2), "=r"(r3) : "r"(addr))

#define MMA_BF16(d, a, b0, b1)                                                 \
    asm volatile("mma.sync.aligned.m16n8k16.row.col.f32.bf16.bf16.f32 "        \
                 "{%0,%1,%2,%3}, {%4,%5,%6,%7}, {%8,%9}, {%0,%1,%2,%3};"       \
                 : "+f"((d)[0]), "+f"((d)[1]), "+f"((d)[2]), "+f"((d)[3])      \
                 : "r"((a)[0]), "r"((a)[1]), "r"((a)[2]), "r"((a)[3]),         \
                   "r"(b0), "r"(b1))

__device__ __forceinline__ uint32_t cvta_smem(const void* p) {
    uint32_t a;
    asm("{ .reg .u64 t; cvta.to.shared.u64 t, %1; cvt.u32.u64 %0, t; }"
        : "=r"(a) : "l"(p));
    return a;
}

// split 4 fp32 -> packed bf16 hi (2 regs) + lo (2 regs)
__device__ __forceinline__ void split4(const float* v, uint32_t* h, uint32_t* l) {
    #pragma unroll
    for (int p = 0; p < 2; ++p) {
        float a = v[2 * p], b = v[2 * p + 1];
        __nv_bfloat162 hh = __floats2bfloat162_rn(a, b);
        float ra = a - __bfloat162float(__low2bfloat16(hh));
        float rb = b - __bfloat162float(__high2bfloat16(hh));
        __nv_bfloat162 ll = __floats2bfloat162_rn(ra, rb);
        h[p] = *(uint32_t*)&hh;
        l[p] = *(uint32_t*)&ll;
    }
}

// ---------------- main kernel ----------------
__global__ __launch_bounds__(NTH, 1)
void subject_mma_kernel(const float* __restrict__ x,
                        const float* __restrict__ w,
                        float* __restrict__ out) {
    extern __shared__ __align__(1024) char smem[];
    const uint32_t sb = cvta_smem(smem);

    const int tid  = threadIdx.x;
    const int wid  = tid >> 5;
    const int lane = tid & 31;

    const int t0 = blockIdx.x * BN;
    const int d0 = blockIdx.y * BM;
    const int b  = blockIdx.z;

    const float* __restrict__ W = w   + g_subj[b] * (C_IN * D_OUT);
    const float* __restrict__ X = x   + b * (C_IN * T_DIM);
    float*       __restrict__ O = out + b * (D_OUT * T_DIM);

    // warp layout: 2 (d) x 4 (t); warp tile 64(d) x 32(t)
    const int wd = wid >> 2;
    const int wt = wid & 3;
    const int mrem = D_OUT - d0 - wd * 64;
    const int mv = (mrem <= 0) ? 0 : (mrem >= 64 ? 4 : ((mrem + 15) >> 4));
    const int nrem = T_DIM - t0 - wt * 32;
    const int nv = (nrem <= 0) ? 0 : (nrem >= 32 ? 4 : ((nrem + 7) >> 3));

    float acc[4][4][4];
    #pragma unroll
    for (int i = 0; i < 4; ++i)
        #pragma unroll
        for (int j = 0; j < 4; ++j)
            #pragma unroll
            for (int q = 0; q < 4; ++q)
                acc[i][j][q] = 0.0f;

    // LDG staging: 4 granules x 4 fp32, A and B
    float av[4][4], bv[4][4];

    // ---- gmem -> regs (chunk ch) ----
    #define LOAD_CHUNK(ch)                                                     \
        {                                                                      \
            const int c0 = (ch) * BK;                                          \
            _Pragma("unroll")                                                  \
            for (int i = 0; i < 4; ++i) {                                      \
                const int idx = tid + i * NTH;                                 \
                const int c   = idx >> 5;                                      \
                const int g4  = idx & 31;                                      \
                const int cg  = c0 + c;                                        \
                const bool cok = (cg < C_IN);                                  \
                const int dbase = d0 + g4 * 4;                                 \
                const float* wp = W + cg * D_OUT + dbase;                      \
                _Pragma("unroll")                                              \
                for (int j = 0; j < 4; ++j)                                    \
                    av[i][j] = (cok && (dbase + j) < D_OUT) ? __ldg(wp + j)    \
                                                            : 0.0f;           \
                const int tbase = t0 + g4 * 4;                                 \
                if (cok && (tbase + 3) < T_DIM) {                              \
                    const float4 q4 =                                          \
                        *(const float4*)(X + cg * T_DIM + tbase);              \
                    bv[i][0] = q4.x; bv[i][1] = q4.y;                          \
                    bv[i][2] = q4.z; bv[i][3] = q4.w;                          \
                } else {                                                       \
                    const float* xp = X + cg * T_DIM + tbase;                  \
                    _Pragma("unroll")                                          \
                    for (int j = 0; j < 4; ++j)                                \
                        bv[i][j] = (cok && (tbase + j) < T_DIM) ? __ldg(xp + j)\
                                                                : 0.0f;        \
                }                                                              \
            }                                                                  \
        }

    // ---- regs -> smem (stage st) ----
    #define STORE_CHUNK(st)                                                    \
        {                                                                      \
            char* base = smem + (st) * STAGE_SZ;                               \
            _Pragma("unroll")                                                  \
            for (int i = 0; i < 4; ++i) {                                      \
                const int idx = tid + i * NTH;                                 \
                const int c   = idx >> 5;                                      \
                const int g4  = idx & 31;                                      \
                const int off = c * 256 + ((((g4 >> 1) ^ (c & 7)) << 4)        \
                                           | ((g4 & 1) * 8));                  \
                uint32_t h[2], l[2];                                           \
                split4(av[i], h, l);                                           \
                *(uint2*)(base + ST_A_HI + off) = make_uint2(h[0], h[1]);      \
                *(uint2*)(base + ST_A_LO + off) = make_uint2(l[0], l[1]);      \
                split4(bv[i], h, l);                                           \
                *(uint2*)(base + ST_B_HI + off) = make_uint2(h[0], h[1]);      \
                *(uint2*)(base + ST_B_LO + off) = make_uint2(l[0], l[1]);      \
            }                                                                  \
        }

    const int g = lane >> 3;     // ldmatrix matrix-group 0..3
    const int i8 = lane & 7;     // row within matrix

    // ---- compute one BK=32 chunk from smem stage ----
    #define COMPUTE_CHUNK(st, MV, NV)                                          \
        {                                                                      \
            const uint32_t base = sb + (st) * STAGE_SZ;                        \
            _Pragma("unroll")                                                  \
            for (int ks = 0; ks < 2; ++ks) {                                   \
                /* B fragments: 2 x4.trans per precision, covering n-tiles */  \
                uint32_t bh[8], bl[8];                                         \
                const int rowB = ks * 16 + (g & 1) * 8 + i8;                   \
                _Pragma("unroll")                                              \
                for (int p = 0; p < 2; ++p) {                                  \
                    const int chunkB = wt * 4 + p * 2 + (g >> 1);              \
                    const uint32_t ab = base + ST_B_HI + rowB * 256            \
                                        + ((uint32_t)(chunkB ^ i8) << 4);      \
                    LDSM_X4_T(bh[p*4+0], bh[p*4+1], bh[p*4+2], bh[p*4+3], ab); \
                    LDSM_X4_T(bl[p*4+0], bl[p*4+1], bl[p*4+2], bl[p*4+3],      \
                              ab + (ST_B_LO - ST_B_HI));                       \
                }                                                              \
                const int rowA = ks * 16 + (g >> 1) * 8 + i8;                  \
                _Pragma("unroll")                                              \
                for (int mi = 0; mi < 4; ++mi) {                               \
                    if (mi < (MV)) {                                           \
                        const int chunkA = wd * 8 + mi * 2 + (g & 1);          \
                        const uint32_t aa = base + ST_A_HI + rowA * 256        \
                                            + ((uint32_t)(chunkA ^ i8) << 4);  \
                        uint32_t ah[4], al[4];                                 \
                        LDSM_X4_T(ah[0], ah[1], ah[2], ah[3], aa);             \
                        LDSM_X4_T(al[0], al[1], al[2], al[3],                  \
                                  aa + (ST_A_LO - ST_A_HI));                   \
                        _Pragma("unroll")                                      \
                        for (int ni = 0; ni < 4; ++ni) {                       \
                            if (ni < (NV)) {                                   \
                                const int bi = (ni >> 1) * 4 + (ni & 1) * 2;   \
                                MMA_BF16(acc[mi][ni], ah, bh[bi], bh[bi + 1]); \
                                MMA_BF16(acc[mi][ni], ah, bl[bi], bl[bi + 1]); \
                                MMA_BF16(acc[mi][ni], al, bh[bi], bh[bi + 1]); \
                            }                                                  \
                        }                                                      \
                    }                                                          \
                }                                                              \
            }                                                                  \
        }

    // ---- pipelined main loop (2-stage smem, reg-staged gmem) ----
    LOAD_CHUNK(0);
    STORE_CHUNK(0);
    const bool full = (mv == 4 && nv == 4);

    for (int ch = 0; ch < NCH; ++ch) {
        if (ch + 1 < NCH) LOAD_CHUNK(ch + 1);
        __syncthreads();
        if (full) { COMPUTE_CHUNK(ch & 1, 4, 4); }
        else      { COMPUTE_CHUNK(ch & 1, mv, nv); }
        if (ch + 1 < NCH) STORE_CHUNK((ch + 1) & 1);
    }

    // ---- epilogue ----
    const int r  = lane >> 2;
    const int cc = (lane & 3) * 2;
    #pragma unroll
    for (int mi = 0; mi < 4; ++mi) {
        #pragma unroll
        for (int ni = 0; ni < 4; ++ni) {
            const int t = t0 + wt * 32 + ni * 8 + cc;
            if (t < T_DIM) {
                const int d1 = d0 + wd * 64 + mi * 16 + r;
                if (d1 < D_OUT)
                    *(float2*)(O + d1 * T_DIM + t) =
                        make_float2(acc[mi][ni][0], acc[mi][ni][1]);
                const int d2 = d1 + 8;
                if (d2 < D_OUT)
                    *(float2*)(O + d2 * T_DIM + t) =
                        make_float2(acc[mi][ni][2], acc[mi][ni][3]);
            }
        }
    }

    #undef LOAD_CHUNK
    #undef STORE_CHUNK
    #undef COMPUTE_CHUNK
}

extern "C" void kernel_launch(void* const* d_in, const int* in_sizes, int n_in,
                              void* d_out, int out_size) {
    const float* x        = (const float*)d_in[0];
    const void*  subjects = d_in[1];
    const float* weights  = (const float*)d_in[2];
    float* out            = (float*)d_out;

    decode_subjects_kernel<<<1, 256>>>(subjects);

    cudaFuncSetAttribute(subject_mma_kernel,
                         cudaFuncAttributeMaxDynamicSharedMemorySize, SMEM_TOTAL);
    dim3 grid(3, 3, N_BATCH);    // t-tiles, d-tiles, samples
    subject_mma_kernel<<<grid, NTH, SMEM_TOTAL>>>(x, weights, out);
}

// round 4
// speedup vs baseline: 1.7032x; 1.1340x over previous
#include <cuda_runtime.h>
#include <cuda_bf16.h>
#include <cstdint>

// ---------------- problem constants ----------------
#define C_IN    273
#define D_OUT   273
#define T_DIM   360
#define N_BATCH 256

// ---------------- tiling ----------------
#define BM 128
#define BN 128
#define BK 32
#define NCH 9          // ceil(273/32)
#define NTH 512        // 16 warps: 4(d) x 4(t), warp tile 32x32

// SMEM stage layout (bf16 tiles, 32 rows x 128 cols each)
#define ST_A_HI 0
#define ST_A_LO 8192
#define ST_B_HI 16384
#define ST_B_LO 24576
#define STAGE_SZ 32768
#define SMEM_TOTAL (2 * STAGE_SZ)   // 65536

__device__ int g_subj[N_BATCH];

__global__ void decode_subjects_kernel(const void* __restrict__ subj_raw) {
    __shared__ int is64_s;
    const int tid = threadIdx.x;
    if (tid == 0) {
        const long long* ll = (const long long*)subj_raw;
        int ok = 1;
        for (int i = 0; i < 128; ++i) {         // reads only first 1024 B
            long long v = ll[i];
            if (v < 0 || v >= 128) { ok = 0; break; }
        }
        is64_s = ok;
    }
    __syncthreads();
    const int is64 = is64_s;
    for (int b = tid; b < N_BATCH; b += blockDim.x) {
        g_subj[b] = is64 ? (int)(((const long long*)subj_raw)[b])
                         : ((const int*)subj_raw)[b];
    }
}

// ---------------- PTX helpers (sm_80-level ISA only) ----------------
#define LDSM_X4_T(r0, r1, r2, r3, addr)                                        \
    asm volatile("ldmatrix.sync.aligned.m8n8.x4.trans.shared.b16 "             \
                 "{%0,%1,%2,%3}, [%4];"                                        \
                 : "=r"(r0), "=r"(r1), "=r"(r2), "=r"(r3) : "r"(addr))

#define MMA_BF16(d, a, b0, b1)                                                 \
    asm volatile("mma.sync.aligned.m16n8k16.row.col.f32.bf16.bf16.f32 "        \
                 "{%0,%1,%2,%3}, {%4,%5,%6,%7}, {%8,%9}, {%0,%1,%2,%3};"       \
                 : "+f"((d)[0]), "+f"((d)[1]), "+f"((d)[2]), "+f"((d)[3])      \
                 : "r"((a)[0]), "r"((a)[1]), "r"((a)[2]), "r"((a)[3]),         \
                   "r"(b0), "r"(b1))

__device__ __forceinline__ uint32_t cvta_smem(const void* p) {
    uint32_t a;
    asm("{ .reg .u64 t; cvta.to.shared.u64 t, %1; cvt.u32.u64 %0, t; }"
        : "=r"(a) : "l"(p));
    return a;
}

// split 4 fp32 -> packed bf16 hi (2 regs) + lo (2 regs)
__device__ __forceinline__ void split4(const float* v, uint32_t* h, uint32_t* l) {
    #pragma unroll
    for (int p = 0; p < 2; ++p) {
        float a = v[2 * p], b = v[2 * p + 1];
        __nv_bfloat162 hh = __floats2bfloat162_rn(a, b);
        float ra = a - __bfloat162float(__low2bfloat16(hh));
        float rb = b - __bfloat162float(__high2bfloat16(hh));
        __nv_bfloat162 ll = __floats2bfloat162_rn(ra, rb);
        h[p] = *(uint32_t*)&hh;
        l[p] = *(uint32_t*)&ll;
    }
}

// ---------------- main kernel ----------------
__global__ __launch_bounds__(NTH, 1)
void subject_mma_kernel(const float* __restrict__ x,
                        const float* __restrict__ w,
                        float* __restrict__ out) {
    extern __shared__ __align__(1024) char smem[];
    const uint32_t sb = cvta_smem(smem);

    const int tid  = threadIdx.x;
    const int wid  = tid >> 5;
    const int lane = tid & 31;

    const int t0 = blockIdx.x * BN;
    const int d0 = blockIdx.y * BM;
    const int b  = blockIdx.z;

    const float* __restrict__ W = w   + g_subj[b] * (C_IN * D_OUT);
    const float* __restrict__ X = x   + b * (C_IN * T_DIM);
    float*       __restrict__ O = out + b * (D_OUT * T_DIM);

    // warp layout: 4 (d) x 4 (t); warp tile 32(d) x 32(t)
    const int wd = wid >> 2;
    const int wt = wid & 3;
    const int mrem = D_OUT - d0 - wd * 32;
    const int mv = (mrem <= 0) ? 0 : (mrem >= 32 ? 2 : ((mrem + 15) >> 4));
    const int nrem = T_DIM - t0 - wt * 32;
    const int nv = (nrem <= 0) ? 0 : (nrem >= 32 ? 4 : ((nrem + 7) >> 3));

    float acc[2][4][4];
    #pragma unroll
    for (int i = 0; i < 2; ++i)
        #pragma unroll
        for (int j = 0; j < 4; ++j)
            #pragma unroll
            for (int q = 0; q < 4; ++q)
                acc[i][j][q] = 0.0f;

    // LDG staging: 2 granules x 4 fp32, A and B
    float av[2][4], bv[2][4];

    // ---- gmem -> regs (chunk ch) ----
    #define LOAD_CHUNK(ch)                                                     \
        {                                                                      \
            const int c0 = (ch) * BK;                                          \
            _Pragma("unroll")                                                  \
            for (int i = 0; i < 2; ++i) {                                      \
                const int idx = tid + i * NTH;                                 \
                const int c   = idx >> 5;                                      \
                const int g4  = idx & 31;                                      \
                const int cg  = c0 + c;                                        \
                const bool cok = (cg < C_IN);                                  \
                const int dbase = d0 + g4 * 4;                                 \
                const float* wp = W + cg * D_OUT + dbase;                      \
                _Pragma("unroll")                                              \
                for (int j = 0; j < 4; ++j)                                    \
                    av[i][j] = (cok && (dbase + j) < D_OUT) ? __ldg(wp + j)    \
                                                            : 0.0f;           \
                const int tbase = t0 + g4 * 4;                                 \
                if (cok && (tbase + 3) < T_DIM) {                              \
                    const float4 q4 =                                          \
                        *(const float4*)(X + cg * T_DIM + tbase);              \
                    bv[i][0] = q4.x; bv[i][1] = q4.y;                          \
                    bv[i][2] = q4.z; bv[i][3] = q4.w;                          \
                } else {                                                       \
                    const float* xp = X + cg * T_DIM + tbase;                  \
                    _Pragma("unroll")                                          \
                    for (int j = 0; j < 4; ++j)                                \
                        bv[i][j] = (cok && (tbase + j) < T_DIM) ? __ldg(xp + j)\
                                                                : 0.0f;        \
                }                                                              \
            }                                                                  \
        }

    // ---- regs -> smem (stage st) ----
    #define STORE_CHUNK(st)                                                    \
        {                                                                      \
            char* base = smem + (st) * STAGE_SZ;                               \
            _Pragma("unroll")                                                  \
            for (int i = 0; i < 2; ++i) {                                      \
                const int idx = tid + i * NTH;                                 \
                const int c   = idx >> 5;                                      \
                const int g4  = idx & 31;                                      \
                const int off = c * 256 + ((((g4 >> 1) ^ (c & 7)) << 4)        \
                                           | ((g4 & 1) * 8));                  \
                uint32_t h[2], l[2];                                           \
                split4(av[i], h, l);                                           \
                *(uint2*)(base + ST_A_HI + off) = make_uint2(h[0], h[1]);      \
                *(uint2*)(base + ST_A_LO + off) = make_uint2(l[0], l[1]);      \
                split4(bv[i], h, l);                                           \
                *(uint2*)(base + ST_B_HI + off) = make_uint2(h[0], h[1]);      \
                *(uint2*)(base + ST_B_LO + off) = make_uint2(l[0], l[1]);      \
            }                                                                  \
        }

    const int g = lane >> 3;     // ldmatrix matrix-group 0..3
    const int i8 = lane & 7;     // row within matrix

    // ---- compute one BK=32 chunk from smem stage ----
    #define COMPUTE_CHUNK(st, MV, NV)                                          \
        {                                                                      \
            const uint32_t base = sb + (st) * STAGE_SZ;                        \
            _Pragma("unroll")                                                  \
            for (int ks = 0; ks < 2; ++ks) {                                   \
                uint32_t bh[8], bl[8];                                         \
                const int rowB = ks * 16 + (g & 1) * 8 + i8;                   \
                _Pragma("unroll")                                              \
                for (int p = 0; p < 2; ++p) {                                  \
                    const int chunkB = wt * 4 + p * 2 + (g >> 1);              \
                    const uint32_t ab = base + ST_B_HI + rowB * 256            \
                                        + ((uint32_t)(chunkB ^ i8) << 4);      \
                    LDSM_X4_T(bh[p*4+0], bh[p*4+1], bh[p*4+2], bh[p*4+3], ab); \
                    LDSM_X4_T(bl[p*4+0], bl[p*4+1], bl[p*4+2], bl[p*4+3],      \
                              ab + (ST_B_LO - ST_B_HI));                       \
                }                                                              \
                const int rowA = ks * 16 + (g >> 1) * 8 + i8;                  \
                _Pragma("unroll")                                              \
                for (int mi = 0; mi < 2; ++mi) {                               \
                    if (mi < (MV)) {                                           \
                        const int chunkA = wd * 4 + mi * 2 + (g & 1);          \
                        const uint32_t aa = base + ST_A_HI + rowA * 256        \
                                            + ((uint32_t)(chunkA ^ i8) << 4);  \
                        uint32_t ah[4], al[4];                                 \
                        LDSM_X4_T(ah[0], ah[1], ah[2], ah[3], aa);             \
                        LDSM_X4_T(al[0], al[1], al[2], al[3],                  \
                                  aa + (ST_A_LO - ST_A_HI));                   \
                        _Pragma("unroll")                                      \
                        for (int ni = 0; ni < 4; ++ni) {                       \
                            if (ni < (NV)) {                                   \
                                const int bi = (ni >> 1) * 4 + (ni & 1) * 2;   \
                                MMA_BF16(acc[mi][ni], ah, bh[bi], bh[bi + 1]); \
                                MMA_BF16(acc[mi][ni], ah, bl[bi], bl[bi + 1]); \
                                MMA_BF16(acc[mi][ni], al, bh[bi], bh[bi + 1]); \
                            }                                                  \
                        }                                                      \
                    }                                                          \
                }                                                              \
            }                                                                  \
        }

    // ---- pipelined main loop (2-stage smem, reg-staged gmem) ----
    LOAD_CHUNK(0);
    STORE_CHUNK(0);
    const bool full = (mv == 2 && nv == 4);

    for (int ch = 0; ch < NCH; ++ch) {
        if (ch + 1 < NCH) LOAD_CHUNK(ch + 1);
        __syncthreads();
        if (full) { COMPUTE_CHUNK(ch & 1, 2, 4); }
        else      { COMPUTE_CHUNK(ch & 1, mv, nv); }
        if (ch + 1 < NCH) STORE_CHUNK((ch + 1) & 1);
    }

    // ---- epilogue ----
    const int r  = lane >> 2;
    const int cc = (lane & 3) * 2;
    #pragma unroll
    for (int mi = 0; mi < 2; ++mi) {
        #pragma unroll
        for (int ni = 0; ni < 4; ++ni) {
            const int t = t0 + wt * 32 + ni * 8 + cc;
            if (t < T_DIM) {
                const int d1 = d0 + wd * 32 + mi * 16 + r;
                if (d1 < D_OUT)
                    *(float2*)(O + d1 * T_DIM + t) =
                        make_float2(acc[mi][ni][0], acc[mi][ni][1]);
                const int d2 = d1 + 8;
                if (d2 < D_OUT)
                    *(float2*)(O + d2 * T_DIM + t) =
                        make_float2(acc[mi][ni][2], acc[mi][ni][3]);
            }
        }
    }

    #undef LOAD_CHUNK
    #undef STORE_CHUNK
    #undef COMPUTE_CHUNK
}

extern "C" void kernel_launch(void* const* d_in, const int* in_sizes, int n_in,
                              void* d_out, int out_size) {
    const float* x        = (const float*)d_in[0];
    const void*  subjects = d_in[1];
    const float* weights  = (const float*)d_in[2];
    float* out            = (float*)d_out;

    decode_subjects_kernel<<<1, 256>>>(subjects);

    cudaFuncSetAttribute(subject_mma_kernel,
                         cudaFuncAttributeMaxDynamicSharedMemorySize, SMEM_TOTAL);
    dim3 grid(3, 3, N_BATCH);    // t-tiles, d-tiles, samples
    subject_mma_kernel<<<grid, NTH, SMEM_TOTAL>>>(x, weights, out);
}